// round 8
// baseline (speedup 1.0000x reference)
#include <cuda_runtime.h>

#define IMG_H 2048
#define IMG_W 2048

constexpr int STRIP = 16;   // output rows per thread
constexpr int BLKT  = 128;  // threads per block (each owns 4 columns)

__device__ __forceinline__ float4 f4add(float4 a, float4 b) {
    return make_float4(a.x+b.x, a.y+b.y, a.z+b.z, a.w+b.w);
}
__device__ __forceinline__ float4 f4sub(float4 a, float4 b) {
    return make_float4(a.x-b.x, a.y-b.y, a.z-b.z, a.w-b.w);
}
__device__ __forceinline__ float4 f4fma(float w, float4 a, float4 acc) {
    return make_float4(fmaf(w,a.x,acc.x), fmaf(w,a.y,acc.y),
                       fmaf(w,a.z,acc.z), fmaf(w,a.w,acc.w));
}

// Horizontal pass for one image row: S(c)=box7, D(c)=Σk·v, c = gx0..gx0+3.
__device__ __forceinline__ void hpass(const float* __restrict__ row, int gx0,
                                      bool interior, float4& S, float4& D) {
    float f[12];  // cols gx0-4 .. gx0+7
    if (interior) {
        float4 a = *reinterpret_cast<const float4*>(row + gx0 - 4);
        float4 b = *reinterpret_cast<const float4*>(row + gx0);
        float4 c = *reinterpret_cast<const float4*>(row + gx0 + 4);
        f[0]=a.x; f[1]=a.y; f[2]=a.z;  f[3]=a.w;
        f[4]=b.x; f[5]=b.y; f[6]=b.z;  f[7]=b.w;
        f[8]=c.x; f[9]=c.y; f[10]=c.z; f[11]=c.w;
    } else {
        #pragma unroll
        for (int m = 0; m < 12; m++) {
            int gc = min(max(gx0 - 4 + m, 0), IMG_W - 1);
            f[m] = row[gc];
        }
    }
    float S0 = f[1]+f[2]+f[3]+f[4]+f[5]+f[6]+f[7];
    float S1 = S0 - f[1] + f[8];
    float S2 = S1 - f[2] + f[9];
    float S3 = S2 - f[3] + f[10];
    float D0 = -3.0f*f[1] - 2.0f*f[2] - f[3] + f[5] + 2.0f*f[6] + 3.0f*f[7];
    float D1 = D0 + 3.0f*f[1] + 4.0f*f[8]  - S1;
    float D2 = D1 + 3.0f*f[2] + 4.0f*f[9]  - S2;
    float D3 = D2 + 3.0f*f[3] + 4.0f*f[10] - S3;
    S = make_float4(S0, S1, S2, S3);
    D = make_float4(D0, D1, D2, D3);
}

__global__ __launch_bounds__(BLKT, 5)
void plane_fit_kernel(const float* __restrict__ x, float* __restrict__ out) {
    const int gx0 = (blockIdx.x * BLKT + threadIdx.x) * 4;  // first of 4 owned cols
    const int gy0 = blockIdx.y * STRIP;                     // first output row
    const bool interior = (gx0 >= 4) && (gx0 + 7 <= IMG_W - 1);

    const float inv196 = 1.0f / 196.0f;
    const float inv49  = 1.0f / 49.0f;

    float4 rS[7], rD[7];

    // ---- warmup: extended rows e = 0..5  (image rows gy0-3 .. gy0+2, clamped) ----
    #pragma unroll
    for (int e = 0; e < 6; e++) {
        const int gy = min(max(gy0 - 3 + e, 0), IMG_H - 1);
        hpass(x + (size_t)gy * IMG_W, gx0, interior, rS[e], rD[e]);
    }

    float4 sS, sY, sD;

    // ---- main: 16 output rows, ring slot (r+6)%7 == (r-1)%7 ----
    #pragma unroll
    for (int r = 0; r < STRIP; r++) {
        const int e    = r + 6;
        const int slot = e % 7;
        const int gy   = min(gy0 - 3 + e, IMG_H - 1);  // only bottom clamp can trigger here
        float4 Sn, Dn;
        hpass(x + (size_t)gy * IMG_W, gx0, interior, Sn, Dn);

        if (r == 0) {
            rS[6] = Sn; rD[6] = Dn;
            sS = rS[0]; sD = rD[0];
            sY = make_float4(-3.f*rS[0].x, -3.f*rS[0].y, -3.f*rS[0].z, -3.f*rS[0].w);
            #pragma unroll
            for (int k = 1; k < 7; k++) {
                const float w = (float)(k - 3);
                sS = f4add(sS, rS[k]);
                sY = f4fma(w, rS[k], sY);
                sD = f4add(sD, rD[k]);
            }
        } else {
            const float4 Sl = rS[slot];
            const float4 Dl = rD[slot];
            rS[slot] = Sn; rD[slot] = Dn;
            // sY' = sY - sS + 4*S_leave + 3*S_enter   (uses OLD sS)
            sY = f4fma(4.f, Sl, f4fma(3.f, Sn, f4sub(sY, sS)));
            sS = f4add(f4sub(sS, Sl), Sn);
            sD = f4add(f4sub(sD, Dl), Dn);
        }

        // ---- store output row gy0+r: 3 packed float4 (12 floats = 4 px * 3 ch) ----
        float* __restrict__ o = out + ((size_t)(gy0 + r) * IMG_W + gx0) * 3;
        float4 p0 = make_float4(sD.x*inv196, sY.x*inv196, sS.x*inv49, sD.y*inv196);
        float4 p1 = make_float4(sY.y*inv196, sS.y*inv49,  sD.z*inv196, sY.z*inv196);
        float4 p2 = make_float4(sS.z*inv49,  sD.w*inv196, sY.w*inv196, sS.w*inv49);
        __stcs(reinterpret_cast<float4*>(o) + 0, p0);
        __stcs(reinterpret_cast<float4*>(o) + 1, p1);
        __stcs(reinterpret_cast<float4*>(o) + 2, p2);
    }
}

extern "C" void kernel_launch(void* const* d_in, const int* in_sizes, int n_in,
                              void* d_out, int out_size) {
    const float* x = (const float*)d_in[0];
    float* out = (float*)d_out;
    dim3 block(BLKT);
    dim3 grid(IMG_W / (BLKT * 4), IMG_H / STRIP);  // (4, 128) = 512 blocks
    plane_fit_kernel<<<grid, block>>>(x, out);
}